// round 2
// baseline (speedup 1.0000x reference)
#include <cuda_runtime.h>
#include <cstdint>

#define BB 4
#define LL 2048
#define DD 512
#define NLAY 2
#define EDIM 1024
#define NSTATE 16
#define RRANK 32
#define KCONV 4
#define MM (BB*LL)   // 8192 tokens

// ---------------- scratch (static device allocations; no cudaMalloc allowed) ----
__device__ float g_u[(size_t)MM * DD];            // 16 MB   normed input
__device__ float g_xz[(size_t)MM * 2 * EDIM];     // 64 MB   in-proj output
__device__ float g_xc[(size_t)MM * EDIM];         // 32 MB   conv+silu output
__device__ float g_dbc[(size_t)MM * 64];          //  2 MB   x-proj output (dt|B|C)
__device__ float g_delta[(size_t)MM * EDIM];      // 32 MB   softplus(dt proj)
__device__ float g_y[(size_t)MM * EDIM];          // 32 MB   scan output

// ---------------- rmsnorm: one block per token row of 512 -----------------------
__global__ void rmsnorm_kernel(const float* __restrict__ x,
                               const float* __restrict__ w,
                               float* __restrict__ out) {
    int m = blockIdx.x;
    int tid = threadIdx.x;  // 128 threads, 4 floats each
    float4 v = reinterpret_cast<const float4*>(x + (size_t)m * DD)[tid];
    float ss = v.x * v.x + v.y * v.y + v.z * v.z + v.w * v.w;
    #pragma unroll
    for (int o = 16; o; o >>= 1) ss += __shfl_xor_sync(0xffffffffu, ss, o);
    __shared__ float red[4];
    if ((tid & 31) == 0) red[tid >> 5] = ss;
    __syncthreads();
    float tot = red[0] + red[1] + red[2] + red[3];
    float rs = rsqrtf(tot * (1.0f / DD) + 1e-5f);
    float4 wv = reinterpret_cast<const float4*>(w)[tid];
    float4 o4 = make_float4(v.x * rs * wv.x, v.y * rs * wv.y,
                            v.z * rs * wv.z, v.w * rs * wv.w);
    reinterpret_cast<float4*>(out + (size_t)m * DD)[tid] = o4;
}

// ---------------- tiled fp32 GEMM: C[M,N] = A[M,K] * B[N,K]^T (+ epilogue) ------
// EPI 0: plain store
// EPI 1: C = softplus(acc + bias[n])
// EPI 2: C = (C + acc) * mask[m]   (residual update in-place)
template<int BM, int BN, int BK, int TM, int TN, int EPI>
__global__ __launch_bounds__(256)
void gemm_kernel(const float* __restrict__ A, const float* __restrict__ Bw,
                 float* __restrict__ C, int M, int N, int K,
                 int lda, int ldb, int ldc,
                 const float* __restrict__ bias, const int* __restrict__ mask) {
    constexpr int TX = BN / TN;
    constexpr int TY = BM / TM;
    constexpr int THREADS = TX * TY;   // 256
    constexpr int KV = BK / 4;
    __shared__ float As[BK][BM];
    __shared__ float Bs[BK][BN];

    int tid = threadIdx.x;
    int tx = tid % TX, ty = tid / TX;
    int bm = blockIdx.y * BM, bn = blockIdx.x * BN;
    const float* Ab = A + (size_t)bm * lda;
    const float* Bb = Bw + (size_t)bn * ldb;

    float acc[TM][TN];
    #pragma unroll
    for (int i = 0; i < TM; i++)
        #pragma unroll
        for (int j = 0; j < TN; j++) acc[i][j] = 0.f;

    for (int kt = 0; kt < K; kt += BK) {
        #pragma unroll
        for (int i = 0; i < (BM * KV) / THREADS; i++) {
            int idx = tid + i * THREADS;
            int r = idx / KV, c = idx % KV;
            float4 v = *reinterpret_cast<const float4*>(Ab + (size_t)r * lda + kt + c * 4);
            As[c * 4 + 0][r] = v.x; As[c * 4 + 1][r] = v.y;
            As[c * 4 + 2][r] = v.z; As[c * 4 + 3][r] = v.w;
        }
        #pragma unroll
        for (int i = 0; i < (BN * KV) / THREADS; i++) {
            int idx = tid + i * THREADS;
            int r = idx / KV, c = idx % KV;
            float4 v = *reinterpret_cast<const float4*>(Bb + (size_t)r * ldb + kt + c * 4);
            Bs[c * 4 + 0][r] = v.x; Bs[c * 4 + 1][r] = v.y;
            Bs[c * 4 + 2][r] = v.z; Bs[c * 4 + 3][r] = v.w;
        }
        __syncthreads();
        #pragma unroll
        for (int k = 0; k < BK; k++) {
            float ra[TM], rb[TN];
            #pragma unroll
            for (int i = 0; i < TM; i++) ra[i] = As[k][ty * TM + i];
            #pragma unroll
            for (int j = 0; j < TN; j++) rb[j] = Bs[k][tx * TN + j];
            #pragma unroll
            for (int i = 0; i < TM; i++)
                #pragma unroll
                for (int j = 0; j < TN; j++) acc[i][j] += ra[i] * rb[j];
        }
        __syncthreads();
    }

    #pragma unroll
    for (int i = 0; i < TM; i++) {
        int m = bm + ty * TM + i;
        float maskf = 1.f;
        if (EPI == 2) maskf = (float)mask[m];
        #pragma unroll
        for (int j = 0; j < TN; j++) {
            int n = bn + tx * TN + j;
            float v = acc[i][j];
            if (EPI == 1) {
                float s = v + bias[n];
                v = (s > 20.f) ? s : log1pf(__expf(s));
            }
            size_t idx = (size_t)m * ldc + n;
            if (EPI == 2) v = (C[idx] + v) * maskf;
            C[idx] = v;
        }
    }
}

// ---------------- depthwise causal conv (K=4) + bias + silu ---------------------
__global__ void conv_silu_kernel(const float* __restrict__ xz,
                                 const float* __restrict__ w,
                                 const float* __restrict__ b,
                                 float* __restrict__ xc) {
    int id = blockIdx.x * blockDim.x + threadIdx.x;   // over MM*EDIM
    if (id >= MM * EDIM) return;
    int e = id & (EDIM - 1);
    int mt = id >> 10;            // b*L + t
    int t = mt & (LL - 1);
    float w0 = w[e * 4 + 0], w1 = w[e * 4 + 1], w2 = w[e * 4 + 2], w3 = w[e * 4 + 3];
    const float* base = xz + (size_t)mt * (2 * EDIM) + e;
    float x0 = (t >= 3) ? base[-3 * 2 * EDIM] : 0.f;
    float x1 = (t >= 2) ? base[-2 * 2 * EDIM] : 0.f;
    float x2 = (t >= 1) ? base[-1 * 2 * EDIM] : 0.f;
    float x3 = base[0];
    float acc = b[e] + w0 * x0 + w1 * x1 + w2 * x2 + w3 * x3;
    acc = acc * (1.f / (1.f + __expf(-acc)));   // silu
    xc[id] = acc;
}

// ---------------- selective scan, thread per (b, e), 16 states in regs ----------
__global__ void scan_kernel(const float* __restrict__ delta,
                            const float* __restrict__ xc,
                            const float* __restrict__ dbc,
                            const float* __restrict__ xz,
                            const float* __restrict__ A_log,
                            const float* __restrict__ Dp,
                            float* __restrict__ y) {
    int b = blockIdx.y;
    int e = blockIdx.x * blockDim.x + threadIdx.x;   // 8 x 128 = 1024

    float a[NSTATE];
    #pragma unroll
    for (int n = 0; n < NSTATE; n++) a[n] = -__expf(A_log[(size_t)e * NSTATE + n]);
    float a0 = a[0];
    bool pw = true;   // A[e,n] == (n+1)*A[e,0] ?  -> exp-powers fast path
    #pragma unroll
    for (int n = 0; n < NSTATE; n++)
        pw = pw && (fabsf(a[n] - a0 * (n + 1)) <= 1e-5f * fabsf(a[n]) + 1e-12f);
    float dpar = Dp[e];

    float h[NSTATE];
    #pragma unroll
    for (int n = 0; n < NSTATE; n++) h[n] = 0.f;

    __shared__ float sBC[64][32];
    const float* dbcb = dbc + (size_t)b * LL * 64;

    for (int t0 = 0; t0 < LL; t0 += 64) {
        __syncthreads();
        for (int i = threadIdx.x; i < 64 * 32; i += 128) {
            int r = i >> 5, c = i & 31;
            sBC[r][c] = dbcb[(size_t)(t0 + r) * 64 + 32 + c];
        }
        __syncthreads();
        for (int i = 0; i < 64; i++) {
            size_t m = (size_t)(b * LL + t0 + i);
            float d  = delta[m * EDIM + e];
            float xv = xc[m * EDIM + e];
            float du = d * xv;
            float dA[NSTATE];
            if (pw) {
                float p = __expf(a0 * d);
                dA[0] = p;
                #pragma unroll
                for (int n = 1; n < NSTATE; n++) dA[n] = dA[n - 1] * p;
            } else {
                #pragma unroll
                for (int n = 0; n < NSTATE; n++) dA[n] = __expf(a[n] * d);
            }
            float yv = 0.f, yv2 = 0.f;
            #pragma unroll
            for (int n = 0; n < NSTATE; n++) {
                h[n] = dA[n] * h[n] + du * sBC[i][n];
                float c = sBC[i][16 + n];
                if (n & 1) yv2 += h[n] * c; else yv += h[n] * c;
            }
            yv += yv2;
            float zv = xz[m * (2 * EDIM) + EDIM + e];
            float sz = zv * (1.f / (1.f + __expf(-zv)));
            y[m * EDIM + e] = (yv + dpar * xv) * sz;
        }
    }
}

// ---------------- init / tail ---------------------------------------------------
__global__ void init_x(const float* __restrict__ x, const int* __restrict__ mask,
                       float* __restrict__ xb) {
    int id = blockIdx.x * blockDim.x + threadIdx.x;
    if (id < MM * DD) xb[id] = x[id] * (float)mask[id >> 9];   // DD = 512
}

__global__ void tail_kernel(const float* __restrict__ xb, float* __restrict__ out) {
    int id = blockIdx.x * blockDim.x + threadIdx.x;  // BB*DD
    if (id < BB * DD) {
        int b = id / DD, d = id % DD;
        out[id] = xb[(size_t)b * LL * DD + d];
    }
}

// ---------------- launch --------------------------------------------------------
extern "C" void kernel_launch(void* const* d_in, const int* in_sizes, int n_in,
                              void* d_out, int out_size) {
    const float* x        = (const float*)d_in[0];
    const int*   mask     = (const int*)d_in[1];
    const float* norm_w   = (const float*)d_in[2];
    const float* in_w     = (const float*)d_in[3];
    const float* conv_w   = (const float*)d_in[4];
    const float* conv_b   = (const float*)d_in[5];
    const float* xproj_w  = (const float*)d_in[6];
    const float* dtproj_w = (const float*)d_in[7];
    const float* dtproj_b = (const float*)d_in[8];
    const float* A_log    = (const float*)d_in[9];
    const float* D_param  = (const float*)d_in[10];
    const float* out_w    = (const float*)d_in[11];

    float* xb   = (float*)d_out;                    // x lives in d_out
    float* tail = xb + (size_t)MM * DD;             // x[:, 0, :]

    float *u, *xzp, *xcp, *dbcp, *deltap, *yp;
    cudaGetSymbolAddress((void**)&u, g_u);
    cudaGetSymbolAddress((void**)&xzp, g_xz);
    cudaGetSymbolAddress((void**)&xcp, g_xc);
    cudaGetSymbolAddress((void**)&dbcp, g_dbc);
    cudaGetSymbolAddress((void**)&deltap, g_delta);
    cudaGetSymbolAddress((void**)&yp, g_y);

    init_x<<<(MM * DD + 255) / 256, 256>>>(x, mask, xb);

    for (int l = 0; l < NLAY; l++) {
        rmsnorm_kernel<<<MM, 128>>>(xb, norm_w + l * DD, u);

        // xz = u @ in_w^T : M=8192, N=2048, K=512
        gemm_kernel<128,128,16,8,8,0><<<dim3(2 * EDIM / 128, MM / 128), 256>>>(
            u, in_w + (size_t)l * 2 * EDIM * DD, xzp,
            MM, 2 * EDIM, DD, DD, DD, 2 * EDIM, nullptr, nullptr);

        conv_silu_kernel<<<(MM * EDIM + 255) / 256, 256>>>(
            xzp, conv_w + (size_t)l * EDIM * KCONV, conv_b + l * EDIM, xcp);

        // dbc = xc @ xproj_w^T : M=8192, N=64, K=1024
        gemm_kernel<64,64,16,4,4,0><<<dim3(1, MM / 64), 256>>>(
            xcp, xproj_w + (size_t)l * 64 * EDIM, dbcp,
            MM, 64, EDIM, EDIM, EDIM, 64, nullptr, nullptr);

        // delta = softplus(dt @ dtproj_w^T + b) : M=8192, N=1024, K=32 (lda=64!)
        gemm_kernel<128,128,16,8,8,1><<<dim3(EDIM / 128, MM / 128), 256>>>(
            dbcp, dtproj_w + (size_t)l * EDIM * RRANK, deltap,
            MM, EDIM, RRANK, 64, RRANK, EDIM, dtproj_b + l * EDIM, nullptr);

        scan_kernel<<<dim3(EDIM / 128, BB), 128>>>(
            deltap, xcp, dbcp, xzp,
            A_log + (size_t)l * EDIM * NSTATE, D_param + l * EDIM, yp);

        // x = (x + y @ out_w^T) * mask : M=8192, N=512, K=1024
        gemm_kernel<128,128,16,8,8,2><<<dim3(DD / 128, MM / 128), 256>>>(
            yp, out_w + (size_t)l * DD * EDIM, xb,
            MM, DD, EDIM, EDIM, EDIM, DD, nullptr, mask);
    }

    tail_kernel<<<(BB * DD + 255) / 256, 256>>>(xb, tail);
}

// round 5
// speedup vs baseline: 3.2476x; 3.2476x over previous
#include <cuda_runtime.h>
#include <cuda_bf16.h>
#include <cstdint>

#define BB 4
#define LL 2048
#define DD 512
#define NLAY 2
#define EDIM 1024
#define NSTATE 16
#define RRANK 32
#define KCONV 4
#define MM (BB*LL)   // 8192 tokens

// ---------------- scratch (static device allocations) ---------------------------
__device__ float g_xz[(size_t)MM * 2 * EDIM];       // in-proj output (fp32)
__device__ float g_xc[(size_t)MM * EDIM];           // conv+silu output (fp32)
__device__ float g_dbc[(size_t)MM * 64];            // x-proj output (dt|B|C)
__device__ float g_delta[(size_t)MM * EDIM];        // softplus(dt proj)
__device__ __nv_bfloat16 g_u_bf[(size_t)MM * DD];       // normed input (bf16)
__device__ __nv_bfloat16 g_xc_bf[(size_t)MM * EDIM];    // xc bf16
__device__ __nv_bfloat16 g_y_bf[(size_t)MM * EDIM];     // scan output bf16
__device__ __nv_bfloat16 g_inw_bf[(size_t)NLAY * 2 * EDIM * DD];
__device__ __nv_bfloat16 g_outw_bf[(size_t)NLAY * DD * EDIM];
__device__ __nv_bfloat16 g_xprojw_bf[(size_t)NLAY * 64 * EDIM];

// ================= helpers ======================================================
__device__ __forceinline__ uint32_t smem_u32(const void* p) {
    uint32_t a;
    asm("{ .reg .u64 t; cvta.to.shared.u64 t, %1; cvt.u32.u64 %0, t; }"
        : "=r"(a) : "l"(p));
    return a;
}
#define SWZ(o) ((o) ^ (((o) >> 3) & 0x70))

__device__ __forceinline__ void ldsm_x4(uint32_t& r0, uint32_t& r1,
                                        uint32_t& r2, uint32_t& r3, uint32_t addr) {
    asm volatile("ldmatrix.sync.aligned.m8n8.x4.shared.b16 {%0,%1,%2,%3}, [%4];"
                 : "=r"(r0), "=r"(r1), "=r"(r2), "=r"(r3) : "r"(addr));
}
__device__ __forceinline__ void mma16816(float* d, const uint32_t* a, const uint32_t* b) {
    asm volatile("mma.sync.aligned.m16n8k16.row.col.f32.bf16.bf16.f32 "
                 "{%0,%1,%2,%3}, {%4,%5,%6,%7}, {%8,%9}, {%0,%1,%2,%3};"
                 : "+f"(d[0]), "+f"(d[1]), "+f"(d[2]), "+f"(d[3])
                 : "r"(a[0]), "r"(a[1]), "r"(a[2]), "r"(a[3]),
                   "r"(b[0]), "r"(b[1]));
}

// ================= bf16 HMMA GEMM: C[M,N] = A[M,K] @ B[N,K]^T ===================
// EPI 0: plain fp32 store.  EPI 2: C = (C + acc) * mask[m]
template<int BN, int EPI>
__global__ __launch_bounds__(256)
void mma_gemm(const __nv_bfloat16* __restrict__ A, const __nv_bfloat16* __restrict__ Bw,
              float* __restrict__ C, int M, int N, int K, int ldc,
              const int* __restrict__ mask) {
    constexpr int BM = 128, BK = 64;
    constexpr int NW = 4, MW = 2;            // warp grid 2 (M) x 4 (N)
    constexpr int WM = BM / MW;              // 64
    constexpr int WN = BN / NW;              // 32 (BN=128) or 16 (BN=64)
    constexpr int MFRAG = WM / 16;           // 4
    constexpr int NFRAG = WN / 8;            // 4 or 2

    __shared__ alignas(1024) char sA[BM * 128];   // 128 rows x 64 bf16 (SW128)
    __shared__ alignas(1024) char sB[BN * 128];

    int tid = threadIdx.x;
    int wid = tid >> 5, lane = tid & 31;
    int bm = blockIdx.y * BM, bn = blockIdx.x * BN;
    int wm = (wid / NW) * WM;
    int wn = (wid % NW) * WN;
    uint32_t sAb = smem_u32(sA), sBb = smem_u32(sB);

    // per-lane ldmatrix base offsets (without k-step term)
    uint32_t aBase[MFRAG];
    #pragma unroll
    for (int i = 0; i < MFRAG; i++)
        aBase[i] = (uint32_t)((wm + i * 16 + (lane & 15)) * 128 + (lane >> 4) * 16);
    uint32_t bBase[NFRAG / 2];
    #pragma unroll
    for (int j = 0; j < NFRAG / 2; j++)
        bBase[j] = (uint32_t)((wn + j * 16 + (lane & 7) + ((lane >> 4) & 1) * 8) * 128
                              + ((lane >> 3) & 1) * 16);

    float acc[MFRAG][NFRAG][4];
    #pragma unroll
    for (int i = 0; i < MFRAG; i++)
        #pragma unroll
        for (int j = 0; j < NFRAG; j++)
            #pragma unroll
            for (int q = 0; q < 4; q++) acc[i][j][q] = 0.f;

    const int nk = K / BK;
    for (int kc = 0; kc < nk; kc++) {
        // ---- stage A (128x64) and B (BNx64) bf16 tiles with SW128 swizzle ----
        #pragma unroll
        for (int i = 0; i < (BM * 8) / 256; i++) {
            int idx = tid + i * 256;
            int r = idx >> 3, c8 = idx & 7;
            uint4 v = *reinterpret_cast<const uint4*>(
                A + (size_t)(bm + r) * K + kc * 64 + c8 * 8);
            *reinterpret_cast<uint4*>(sA + SWZ((uint32_t)(r * 128 + c8 * 16))) = v;
        }
        #pragma unroll
        for (int i = 0; i < (BN * 8) / 256; i++) {
            int idx = tid + i * 256;
            int r = idx >> 3, c8 = idx & 7;
            uint4 v = *reinterpret_cast<const uint4*>(
                Bw + (size_t)(bn + r) * K + kc * 64 + c8 * 8);
            *reinterpret_cast<uint4*>(sB + SWZ((uint32_t)(r * 128 + c8 * 16))) = v;
        }
        __syncthreads();

        // ---- compute: 4 k16 steps ----
        #pragma unroll
        for (int ks = 0; ks < 4; ks++) {
            uint32_t af[MFRAG][4];
            #pragma unroll
            for (int i = 0; i < MFRAG; i++)
                ldsm_x4(af[i][0], af[i][1], af[i][2], af[i][3],
                        sAb + SWZ(aBase[i] + ks * 32));
            uint32_t bf[NFRAG][2];
            #pragma unroll
            for (int j = 0; j < NFRAG / 2; j++) {
                uint32_t r0, r1, r2, r3;
                // B stored [N][K] row-major -> NON-trans ldmatrix gives the
                // correct col-major fragment for mma row.col (elements
                // B[n=t/4][k=2*(t%4)+{0,1}] == required B-frag pairs).
                ldsm_x4(r0, r1, r2, r3, sBb + SWZ(bBase[j] + ks * 32));
                bf[j * 2][0] = r0; bf[j * 2][1] = r1;
                bf[j * 2 + 1][0] = r2; bf[j * 2 + 1][1] = r3;
            }
            #pragma unroll
            for (int i = 0; i < MFRAG; i++)
                #pragma unroll
                for (int j = 0; j < NFRAG; j++)
                    mma16816(acc[i][j], af[i], bf[j]);
        }
        __syncthreads();
    }

    // ---- epilogue ----
    #pragma unroll
    for (int i = 0; i < MFRAG; i++) {
        int r0 = bm + wm + i * 16 + (lane >> 2);
        int r1 = r0 + 8;
        float mk0 = 1.f, mk1 = 1.f;
        if (EPI == 2) { mk0 = (float)mask[r0]; mk1 = (float)mask[r1]; }
        #pragma unroll
        for (int j = 0; j < NFRAG; j++) {
            int c = bn + wn + j * 8 + (lane & 3) * 2;
            size_t i0 = (size_t)r0 * ldc + c;
            size_t i1 = (size_t)r1 * ldc + c;
            float2 v0 = make_float2(acc[i][j][0], acc[i][j][1]);
            float2 v1 = make_float2(acc[i][j][2], acc[i][j][3]);
            if (EPI == 2) {
                float2 o0 = *reinterpret_cast<float2*>(C + i0);
                float2 o1 = *reinterpret_cast<float2*>(C + i1);
                v0 = make_float2((o0.x + v0.x) * mk0, (o0.y + v0.y) * mk0);
                v1 = make_float2((o1.x + v1.x) * mk1, (o1.y + v1.y) * mk1);
            }
            *reinterpret_cast<float2*>(C + i0) = v0;
            *reinterpret_cast<float2*>(C + i1) = v1;
        }
    }
}

// ---------------- fp32 GEMM + softplus (delta projection, K=32) -----------------
template<int BM, int BN, int BK, int TM, int TN>
__global__ __launch_bounds__(256)
void gemm_softplus(const float* __restrict__ A, const float* __restrict__ Bw,
                   float* __restrict__ C, int M, int N, int K,
                   int lda, int ldb, int ldc, const float* __restrict__ bias) {
    constexpr int TX = BN / TN;
    constexpr int KV = BK / 4;
    __shared__ float As[BK][BM];
    __shared__ float Bs[BK][BN];
    int tid = threadIdx.x;
    int tx = tid % TX, ty = tid / TX;
    int bm = blockIdx.y * BM, bn = blockIdx.x * BN;
    const float* Ab = A + (size_t)bm * lda;
    const float* Bb = Bw + (size_t)bn * ldb;
    float acc[TM][TN];
    #pragma unroll
    for (int i = 0; i < TM; i++)
        #pragma unroll
        for (int j = 0; j < TN; j++) acc[i][j] = 0.f;
    for (int kt = 0; kt < K; kt += BK) {
        #pragma unroll
        for (int i = 0; i < (BM * KV) / 256; i++) {
            int idx = tid + i * 256;
            int r = idx / KV, c = idx % KV;
            float4 v = *reinterpret_cast<const float4*>(Ab + (size_t)r * lda + kt + c * 4);
            As[c*4+0][r] = v.x; As[c*4+1][r] = v.y; As[c*4+2][r] = v.z; As[c*4+3][r] = v.w;
        }
        #pragma unroll
        for (int i = 0; i < (BN * KV) / 256; i++) {
            int idx = tid + i * 256;
            int r = idx / KV, c = idx % KV;
            float4 v = *reinterpret_cast<const float4*>(Bb + (size_t)r * ldb + kt + c * 4);
            Bs[c*4+0][r] = v.x; Bs[c*4+1][r] = v.y; Bs[c*4+2][r] = v.z; Bs[c*4+3][r] = v.w;
        }
        __syncthreads();
        #pragma unroll
        for (int k = 0; k < BK; k++) {
            float ra[TM], rb[TN];
            #pragma unroll
            for (int i = 0; i < TM; i++) ra[i] = As[k][ty * TM + i];
            #pragma unroll
            for (int j = 0; j < TN; j++) rb[j] = Bs[k][tx * TN + j];
            #pragma unroll
            for (int i = 0; i < TM; i++)
                #pragma unroll
                for (int j = 0; j < TN; j++) acc[i][j] += ra[i] * rb[j];
        }
        __syncthreads();
    }
    #pragma unroll
    for (int i = 0; i < TM; i++) {
        int m = bm + ty * TM + i;
        #pragma unroll
        for (int j = 0; j < TN; j++) {
            int n = bn + tx * TN + j;
            float s = acc[i][j] + bias[n];
            float v = (s > 20.f) ? s : log1pf(__expf(s));
            C[(size_t)m * ldc + n] = v;
        }
    }
}

// ---------------- rmsnorm -> bf16 ------------------------------------------------
__global__ void rmsnorm_kernel(const float* __restrict__ x,
                               const float* __restrict__ w,
                               __nv_bfloat16* __restrict__ out) {
    int m = blockIdx.x;
    int tid = threadIdx.x;  // 128 threads, 4 floats each
    float4 v = reinterpret_cast<const float4*>(x + (size_t)m * DD)[tid];
    float ss = v.x * v.x + v.y * v.y + v.z * v.z + v.w * v.w;
    #pragma unroll
    for (int o = 16; o; o >>= 1) ss += __shfl_xor_sync(0xffffffffu, ss, o);
    __shared__ float red[4];
    if ((tid & 31) == 0) red[tid >> 5] = ss;
    __syncthreads();
    float tot = red[0] + red[1] + red[2] + red[3];
    float rs = rsqrtf(tot * (1.0f / DD) + 1e-5f);
    float4 wv = reinterpret_cast<const float4*>(w)[tid];
    __nv_bfloat162 p0 = __floats2bfloat162_rn(v.x * rs * wv.x, v.y * rs * wv.y);
    __nv_bfloat162 p1 = __floats2bfloat162_rn(v.z * rs * wv.z, v.w * rs * wv.w);
    uint2 o2 = make_uint2(*reinterpret_cast<uint32_t*>(&p0),
                          *reinterpret_cast<uint32_t*>(&p1));
    reinterpret_cast<uint2*>(out + (size_t)m * DD)[tid] = o2;
}

// ---------------- depthwise causal conv (K=4) + bias + silu ---------------------
__global__ void conv_silu_kernel(const float* __restrict__ xz,
                                 const float* __restrict__ w,
                                 const float* __restrict__ b,
                                 float* __restrict__ xc,
                                 __nv_bfloat16* __restrict__ xc_bf) {
    int id = blockIdx.x * blockDim.x + threadIdx.x;
    if (id >= MM * EDIM) return;
    int e = id & (EDIM - 1);
    int mt = id >> 10;
    int t = mt & (LL - 1);
    float w0 = w[e*4+0], w1 = w[e*4+1], w2 = w[e*4+2], w3 = w[e*4+3];
    const float* base = xz + (size_t)mt * (2 * EDIM) + e;
    float x0 = (t >= 3) ? base[-3 * 2 * EDIM] : 0.f;
    float x1 = (t >= 2) ? base[-2 * 2 * EDIM] : 0.f;
    float x2 = (t >= 1) ? base[-1 * 2 * EDIM] : 0.f;
    float x3 = base[0];
    float acc = b[e] + w0 * x0 + w1 * x1 + w2 * x2 + w3 * x3;
    acc = acc * (1.f / (1.f + __expf(-acc)));
    xc[id] = acc;
    xc_bf[id] = __float2bfloat16(acc);
}

// ---------------- selective scan (smem-staged) -> bf16 y ------------------------
#define SCAN_CH 64
#define SCAN_SMEM ((3 * SCAN_CH * 128 + SCAN_CH * 32) * (int)sizeof(float))

__global__ void scan_kernel(const float* __restrict__ delta,
                            const float* __restrict__ xc,
                            const float* __restrict__ dbc,
                            const float* __restrict__ xz,
                            const float* __restrict__ A_log,
                            const float* __restrict__ Dp,
                            __nv_bfloat16* __restrict__ y) {
    extern __shared__ float sh[];
    float* sD  = sh;                       // [CH][128]
    float* sX  = sh + SCAN_CH * 128;
    float* sZ  = sh + 2 * SCAN_CH * 128;
    float* sBC = sh + 3 * SCAN_CH * 128;   // [CH][32]

    int b = blockIdx.y;
    int tid = threadIdx.x;
    int e0 = blockIdx.x * 128;
    int e = e0 + tid;

    float a[NSTATE];
    #pragma unroll
    for (int n = 0; n < NSTATE; n++) a[n] = -__expf(A_log[(size_t)e * NSTATE + n]);
    float a0 = a[0];
    bool pw = true;
    #pragma unroll
    for (int n = 0; n < NSTATE; n++)
        pw = pw && (fabsf(a[n] - a0 * (n + 1)) <= 1e-5f * fabsf(a[n]) + 1e-12f);
    float dpar = Dp[e];

    float h[NSTATE];
    #pragma unroll
    for (int n = 0; n < NSTATE; n++) h[n] = 0.f;

    const float* dbcb = dbc + (size_t)b * LL * 64;

    for (int t0 = 0; t0 < LL; t0 += SCAN_CH) {
        __syncthreads();
        for (int i = tid; i < SCAN_CH * 32; i += 128) {
            int r = i >> 5, c = i & 31;
            sBC[i] = dbcb[(size_t)(t0 + r) * 64 + 32 + c];
        }
        #pragma unroll 4
        for (int i = tid; i < SCAN_CH * 32; i += 128) {   // float4 granules
            int r = i >> 5, c4 = i & 31;
            size_t m = (size_t)(b * LL + t0 + r);
            reinterpret_cast<float4*>(sD)[i] =
                *reinterpret_cast<const float4*>(delta + m * EDIM + e0 + c4 * 4);
            reinterpret_cast<float4*>(sX)[i] =
                *reinterpret_cast<const float4*>(xc + m * EDIM + e0 + c4 * 4);
            reinterpret_cast<float4*>(sZ)[i] =
                *reinterpret_cast<const float4*>(xz + m * (2 * EDIM) + EDIM + e0 + c4 * 4);
        }
        __syncthreads();

        for (int i = 0; i < SCAN_CH; i++) {
            float d  = sD[i * 128 + tid];
            float xv = sX[i * 128 + tid];
            float zv = sZ[i * 128 + tid];
            float du = d * xv;
            float dA[NSTATE];
            if (pw) {
                float p = __expf(a0 * d);
                dA[0] = p;
                #pragma unroll
                for (int n = 1; n < NSTATE; n++) dA[n] = dA[n - 1] * p;
            } else {
                #pragma unroll
                for (int n = 0; n < NSTATE; n++) dA[n] = __expf(a[n] * d);
            }
            float yv = 0.f, yv2 = 0.f;
            const float* bc = sBC + i * 32;
            #pragma unroll
            for (int n = 0; n < NSTATE; n++) {
                h[n] = dA[n] * h[n] + du * bc[n];
                float c = bc[16 + n];
                if (n & 1) yv2 += h[n] * c; else yv += h[n] * c;
            }
            yv += yv2;
            float sz = zv * (1.f / (1.f + __expf(-zv)));
            size_t m = (size_t)(b * LL + t0 + i);
            y[m * EDIM + e] = __float2bfloat16((yv + dpar * xv) * sz);
        }
    }
}

// ---------------- misc -----------------------------------------------------------
__global__ void init_x(const float* __restrict__ x, const int* __restrict__ mask,
                       float* __restrict__ xb) {
    int id = blockIdx.x * blockDim.x + threadIdx.x;
    if (id < MM * DD) xb[id] = x[id] * (float)mask[id >> 9];
}

__global__ void cvt_bf16(const float* __restrict__ src, __nv_bfloat16* __restrict__ dst, int n) {
    int id = blockIdx.x * blockDim.x + threadIdx.x;
    if (id < n) dst[id] = __float2bfloat16(src[id]);
}

__global__ void tail_kernel(const float* __restrict__ xb, float* __restrict__ out) {
    int id = blockIdx.x * blockDim.x + threadIdx.x;
    if (id < BB * DD) {
        int b = id / DD, d = id % DD;
        out[id] = xb[(size_t)b * LL * DD + d];
    }
}

// ---------------- launch ---------------------------------------------------------
extern "C" void kernel_launch(void* const* d_in, const int* in_sizes, int n_in,
                              void* d_out, int out_size) {
    const float* x        = (const float*)d_in[0];
    const int*   mask     = (const int*)d_in[1];
    const float* norm_w   = (const float*)d_in[2];
    const float* in_w     = (const float*)d_in[3];
    const float* conv_w   = (const float*)d_in[4];
    const float* conv_b   = (const float*)d_in[5];
    const float* xproj_w  = (const float*)d_in[6];
    const float* dtproj_w = (const float*)d_in[7];
    const float* dtproj_b = (const float*)d_in[8];
    const float* A_log    = (const float*)d_in[9];
    const float* D_param  = (const float*)d_in[10];
    const float* out_w    = (const float*)d_in[11];

    float* xb   = (float*)d_out;
    float* tail = xb + (size_t)MM * DD;

    float *xzp, *xcp, *dbcp, *deltap;
    __nv_bfloat16 *ubf, *xcbf, *ybf, *inwbf, *outwbf, *xprojwbf;
    cudaGetSymbolAddress((void**)&xzp, g_xz);
    cudaGetSymbolAddress((void**)&xcp, g_xc);
    cudaGetSymbolAddress((void**)&dbcp, g_dbc);
    cudaGetSymbolAddress((void**)&deltap, g_delta);
    cudaGetSymbolAddress((void**)&ubf, g_u_bf);
    cudaGetSymbolAddress((void**)&xcbf, g_xc_bf);
    cudaGetSymbolAddress((void**)&ybf, g_y_bf);
    cudaGetSymbolAddress((void**)&inwbf, g_inw_bf);
    cudaGetSymbolAddress((void**)&outwbf, g_outw_bf);
    cudaGetSymbolAddress((void**)&xprojwbf, g_xprojw_bf);

    cudaFuncSetAttribute(scan_kernel,
                         cudaFuncAttributeMaxDynamicSharedMemorySize, SCAN_SMEM);

    // weight conversions (once per call)
    {
        int n1 = NLAY * 2 * EDIM * DD;
        cvt_bf16<<<(n1 + 255) / 256, 256>>>(in_w, inwbf, n1);
        int n2 = NLAY * DD * EDIM;
        cvt_bf16<<<(n2 + 255) / 256, 256>>>(out_w, outwbf, n2);
        int n3 = NLAY * 64 * EDIM;
        cvt_bf16<<<(n3 + 255) / 256, 256>>>(xproj_w, xprojwbf, n3);
    }

    init_x<<<(MM * DD + 255) / 256, 256>>>(x, mask, xb);

    for (int l = 0; l < NLAY; l++) {
        rmsnorm_kernel<<<MM, 128>>>(xb, norm_w + l * DD, ubf);

        // xz = u @ in_w^T : M=8192, N=2048, K=512
        mma_gemm<128, 0><<<dim3(2 * EDIM / 128, MM / 128), 256>>>(
            ubf, inwbf + (size_t)l * 2 * EDIM * DD, xzp,
            MM, 2 * EDIM, DD, 2 * EDIM, nullptr);

        conv_silu_kernel<<<(MM * EDIM + 255) / 256, 256>>>(
            xzp, conv_w + (size_t)l * EDIM * KCONV, conv_b + l * EDIM, xcp, xcbf);

        // dbc = xc @ xproj_w^T : M=8192, N=64, K=1024
        mma_gemm<64, 0><<<dim3(1, MM / 128), 256>>>(
            xcbf, xprojwbf + (size_t)l * 64 * EDIM, dbcp,
            MM, 64, EDIM, 64, nullptr);

        // delta = softplus(dt @ dtproj_w^T + b) : K=32, fp32 path
        gemm_softplus<128,128,16,8,8><<<dim3(EDIM / 128, MM / 128), 256>>>(
            dbcp, dtproj_w + (size_t)l * EDIM * RRANK, deltap,
            MM, EDIM, RRANK, 64, RRANK, EDIM, dtproj_b + l * EDIM);

        scan_kernel<<<dim3(EDIM / 128, BB), 128, SCAN_SMEM>>>(
            deltap, xcp, dbcp, xzp,
            A_log + (size_t)l * EDIM * NSTATE, D_param + l * EDIM, ybf);

        // x = (x + y @ out_w^T) * mask : M=8192, N=512, K=1024
        mma_gemm<128, 2><<<dim3(DD / 128, MM / 128), 256>>>(
            ybf, outwbf + (size_t)l * DD * EDIM, xb,
            MM, DD, EDIM, DD, mask);
    }

    tail_kernel<<<(BB * DD + 255) / 256, 256>>>(xb, tail);
}